// round 7
// baseline (speedup 1.0000x reference)
#include <cuda_runtime.h>
#include <cuda_fp16.h>

#define NN 50000
#define NE 800000
#define NET 850000   // NE + NN self-loops
#define HEADS 4
#define HID 64
#define HC 256       // HEADS*HID
#define NT 200000
#define NEG 0.2f
#define EPSN 1e-5f
#define SCAN_CHUNK 512
#define SCAN_BLKS 98          // ceil((NN+1)/512)

typedef unsigned long long ull;
union F2U { ull u; float2 f; };

__device__ __forceinline__ ull pk2(float lo, float hi) {
    ull r; asm("mov.b64 %0, {%1, %2};" : "=l"(r) : "f"(lo), "f"(hi)); return r;
}
#define FFMA2(acc, a, b) asm("fma.rn.f32x2 %0, %1, %2, %0;" : "+l"(acc) : "l"(a), "l"(b))

// ---------------- scratch (static device globals; no runtime alloc) -------
__device__ __half2  g_hh[NN * 128];      // features, half2: [N][32 pairs][4 heads]
__device__ float4   g_es4[NN];           // (h*a_src).sum(-1) per head
__device__ float4   g_ed4[NN];           // (h*a_dst).sum(-1) per head
__device__ float    g_pre[NN * HID];     // pre-GraphNorm features
__device__ float    g_x2[NN * HID];      // layer output
__device__ float    g_stats[256];        // [L1: sum|sumsq (128)] [L2: sum|sumsq (128)]
__device__ float    g_wt[2 * 1024];      // W projected through a_src/a_dst: [layer][IN][8]
__device__ int      g_row[NN + 1];       // CSR row offsets (by dst)
__device__ int      g_cur[NN];           // scatter cursors
__device__ int      g_csrc[NET];         // src node per dst-sorted edge
__device__ int      g_bsum[SCAN_BLKS];   // scan block sums

// ---------------- fused init: zero row/stats + both wt projections --------
__device__ __forceinline__ void wt_body(const float* __restrict__ W,
                                        const float* __restrict__ as,
                                        const float* __restrict__ ad,
                                        int off, int bb) {
    int wid = bb * 8 + (threadIdx.x >> 5);
    int l = threadIdx.x & 31;
    int k = wid >> 3, o = wid & 7, j = o >> 1;
    const float* a = (o & 1) ? ad : as;
    float v = W[k * HC + j * 64 + l] * a[j * 64 + l]
            + W[k * HC + j * 64 + 32 + l] * a[j * 64 + 32 + l];
#pragma unroll
    for (int s = 16; s; s >>= 1) v += __shfl_xor_sync(~0u, v, s);
    if (l == 0) g_wt[off + wid] = v;
}

__global__ void k_init(const float* __restrict__ W1, const float* __restrict__ as1,
                       const float* __restrict__ ad1, const float* __restrict__ W2,
                       const float* __restrict__ as2, const float* __restrict__ ad2) {
    int b = blockIdx.x;
    if (b < 128) {
        int i = b * 256 + threadIdx.x;
        for (int j = i; j <= NN; j += 128 * 256) g_row[j] = 0;
        if (i < 256) g_stats[i] = 0.f;
    } else if (b < 256) {
        wt_body(W1, as1, ad1, 0, b - 128);       // 128 blocks -> IN=128
    } else {
        wt_body(W2, as2, ad2, 1024, b - 256);    // 64 blocks  -> IN=64
    }
}

// ---------------- CSR build ------------------------------------------------
__global__ void k_hist(const int* __restrict__ ei) {
    int e = blockIdx.x * blockDim.x + threadIdx.x;
    if (e >= NET) return;
    int dst = e < NE ? ei[NE + e] : e - NE;
    atomicAdd(&g_row[dst + 1], 1);
}

__global__ void k_scan1() {
    __shared__ int sh[SCAN_CHUNK];
    int t = threadIdx.x;
    int idx = blockIdx.x * SCAN_CHUNK + t;
    sh[t] = (idx <= NN) ? g_row[idx] : 0;
    __syncthreads();
    for (int o = 1; o < SCAN_CHUNK; o <<= 1) {
        int x = (t >= o) ? sh[t - o] : 0;
        __syncthreads();
        sh[t] += x;
        __syncthreads();
    }
    if (idx <= NN) g_row[idx] = sh[t];
    if (t == SCAN_CHUNK - 1) g_bsum[blockIdx.x] = sh[t];
}

__global__ void k_scan2() {
    int l = threadIdx.x;
    int carry = 0;
    for (int base = 0; base < SCAN_BLKS; base += 32) {
        int idx = base + l;
        int v = (idx < SCAN_BLKS) ? g_bsum[idx] : 0;
        int inc = v;
#pragma unroll
        for (int o = 1; o < 32; o <<= 1) {
            int u = __shfl_up_sync(~0u, inc, o);
            if (l >= o) inc += u;
        }
        if (idx < SCAN_BLKS) g_bsum[idx] = inc - v + carry;
        carry += __shfl_sync(~0u, inc, 31);
    }
}

__global__ void k_scan3() {
    int t = threadIdx.x;
    int idx = blockIdx.x * SCAN_CHUNK + t;
    if (idx <= NN) {
        int v = g_row[idx] + g_bsum[blockIdx.x];
        g_row[idx] = v;
        if (idx < NN) g_cur[idx] = v;
    }
}

__global__ void k_scatter(const int* __restrict__ ei) {
    int e = blockIdx.x * blockDim.x + threadIdx.x;
    if (e >= NET) return;
    int src = e < NE ? ei[e] : e - NE;
    int dst = e < NE ? ei[NE + e] : e - NE;
    int pos = atomicAdd(&g_cur[dst], 1);
    g_csrc[pos] = src;
}

// ---------------- GEMM (h = x@W -> half2) + fused attention scores --------
// FFMA2 inner loop: x pre-duplicated as packed (x,x); W float4 = 2 col-pairs.
// 32 rows/block, 256 threads = 64 col-groups (4 cols) x 4 row-groups (8 rows)
template <int IN>
__device__ __forceinline__ void gemm_body(const float* __restrict__ x,
                                          const float* __restrict__ W, int wtOff) {
    __shared__ ull xs2[32 * IN];     // (x,x) per [row][k]
    __shared__ float ws[IN * 8];
    int nb = blockIdx.x * 32;
    int t = threadIdx.x;
    int cg = t & 63, rg = t >> 6;
    for (int i = t; i < 32 * (IN / 4); i += 256) {
        int r = i / (IN / 4), k4 = i % (IN / 4);
        int n = nb + r;
        float4 v = (n < NN) ? ((const float4*)x)[n * (IN / 4) + k4]
                            : make_float4(0.f, 0.f, 0.f, 0.f);
        ull* dst = &xs2[r * IN + k4 * 4];
        dst[0] = pk2(v.x, v.x); dst[1] = pk2(v.y, v.y);
        dst[2] = pk2(v.z, v.z); dst[3] = pk2(v.w, v.w);
    }
    for (int i = t; i < IN * 8; i += 256) ws[i] = g_wt[wtOff + i];
    __syncthreads();
    ull a01[8] = {}, a23[8] = {};      // bits 0 == (0.f, 0.f)
#pragma unroll 4
    for (int k = 0; k < IN; k++) {
        float4 wv = ((const float4*)W)[k * 64 + cg];
        ull w01 = pk2(wv.x, wv.y);
        ull w23 = pk2(wv.z, wv.w);
        const ull* xr = &xs2[rg * 8 * IN + k];
#pragma unroll
        for (int i = 0; i < 8; i++) {
            ull xv = xr[i * IN];
            FFMA2(a01[i], xv, w01);
            FFMA2(a23[i], xv, w23);
        }
    }
    // epilogue: cols 4cg..4cg+3 -> head hd, pairs p0, p0+1 ; layout [pair][head]
    {
        int hd = cg >> 4, p0 = (cg & 15) * 2;
#pragma unroll
        for (int i = 0; i < 8; i++) {
            int n = nb + rg * 8 + i;
            if (n < NN) {
                F2U v01, v23; v01.u = a01[i]; v23.u = a23[i];
                g_hh[n * 128 + p0 * 4 + hd]       = __floats2half2_rn(v01.f.x, v01.f.y);
                g_hh[n * 128 + (p0 + 1) * 4 + hd] = __floats2half2_rn(v23.f.x, v23.f.y);
            }
        }
    }
    // fused scores: thread t -> (row r, output o); e = x_row . wt[:,o] (exact fp32)
    {
        int r = t >> 3, o = t & 7;
        float e = 0.f;
#pragma unroll 4
        for (int k = 0; k < IN; k++) {
            F2U u; u.u = xs2[r * IN + k];
            e += u.f.x * ws[k * 8 + o];
        }
        int n = nb + r;
        if (n < NN) {
            if (o & 1) ((float*)g_ed4)[n * 4 + (o >> 1)] = e;
            else       ((float*)g_es4)[n * 4 + (o >> 1)] = e;
        }
    }
}
__global__ void k_gemm1(const float* __restrict__ x, const float* __restrict__ W) {
    gemm_body<128>(x, W, 0);
}
__global__ void k_gemm2(const float* __restrict__ W) {
    gemm_body<64>(g_x2, W, 1024);
}

// ---------------- single-pass fused GAT: one warp per dst node -------------
// unshifted softmax (logits are O(1); identical after normalization)
// h layout [pair][head]: lane l loads ONE uint4 = all 4 heads of pair l
__global__ void k_gat(const float* __restrict__ b, int statsOff) {
    int t = threadIdx.x, w = t >> 5, l = t & 31;
    int v = blockIdx.x * 16 + w;
    float p0 = 0.f, p1 = 0.f;
    if (v < NN) {
        int beg = g_row[v], end = g_row[v + 1];
        float4 ed = g_ed4[v];
        float s0 = 0.f, s1 = 0.f, s2 = 0.f, s3 = 0.f;
        float2 a0 = {0.f, 0.f}, a1 = {0.f, 0.f}, a2 = {0.f, 0.f}, a3 = {0.f, 0.f};
#pragma unroll 2
        for (int i = beg; i < end; i++) {
            int s = g_csrc[i];                       // broadcast
            float4 es = g_es4[s];                    // broadcast
            float e0 = es.x + ed.x; e0 = fmaxf(e0, NEG * e0);
            float e1 = es.y + ed.y; e1 = fmaxf(e1, NEG * e1);
            float e2 = es.z + ed.z; e2 = fmaxf(e2, NEG * e2);
            float e3 = es.w + ed.w; e3 = fmaxf(e3, NEG * e3);
            float q0 = __expf(e0), q1 = __expf(e1);
            float q2 = __expf(e2), q3 = __expf(e3);
            s0 += q0; s1 += q1; s2 += q2; s3 += q3;
            uint4 hv = *((const uint4*)&g_hh[s * 128 + l * 4]);   // 1 LDG.128
            float2 f0 = __half22float2(*(__half2*)&hv.x);
            float2 f1 = __half22float2(*(__half2*)&hv.y);
            float2 f2 = __half22float2(*(__half2*)&hv.z);
            float2 f3 = __half22float2(*(__half2*)&hv.w);
            a0.x += f0.x * q0; a0.y += f0.y * q0;
            a1.x += f1.x * q1; a1.y += f1.y * q1;
            a2.x += f2.x * q2; a2.y += f2.y * q2;
            a3.x += f3.x * q3; a3.y += f3.y * q3;
        }
        float i0 = 0.25f / s0, i1 = 0.25f / s1;
        float i2 = 0.25f / s2, i3 = 0.25f / s3;
        p0 = a0.x * i0 + a1.x * i1 + a2.x * i2 + a3.x * i3 + b[2 * l];
        p1 = a0.y * i0 + a1.y * i1 + a2.y * i2 + a3.y * i3 + b[2 * l + 1];
        ((float2*)g_pre)[v * 32 + l] = make_float2(p0, p1);
    }
    // GraphNorm stats: block-reduce over 16 warps, 128 atomics per block
    __shared__ float ss0[512], sq0[512], ss1[512], sq1[512];
    ss0[t] = p0; sq0[t] = p0 * p0; ss1[t] = p1; sq1[t] = p1 * p1;
    __syncthreads();
    if (t < 64) {
        int lane = t >> 1, sel = t & 1;
        const float* sv = sel ? ss1 : ss0;
        const float* qv = sel ? sq1 : sq0;
        float a = 0.f, q = 0.f;
#pragma unroll
        for (int ww = 0; ww < 16; ww++) { a += sv[ww * 32 + lane]; q += qv[ww * 32 + lane]; }
        atomicAdd(&g_stats[statsOff + t], a);        // feature t = 2*lane + sel
        atomicAdd(&g_stats[statsOff + 64 + t], q);
    }
}

// GraphNorm affine + ReLU, stats derived inline
__global__ void k_norm(const float* __restrict__ w, const float* __restrict__ bb,
                       const float* __restrict__ gs, int statsOff) {
    int i = blockIdx.x * blockDim.x + threadIdx.x;
    if (i >= NN * HID) return;
    int c = i & 63;
    float mu = g_stats[statsOff + c] * (1.f / NN);
    float m2 = g_stats[statsOff + 64 + c] * (1.f / NN);
    float sc = gs[c];
    float var = m2 - 2.f * sc * mu * mu + sc * sc * mu * mu;
    float v = (g_pre[i] - mu * sc) * rsqrtf(var + EPSN) * w[c] + bb[c];
    g_x2[i] = v > 0.f ? v : 0.f;
}

// one warp per triplet: gather 4x64, layernorm(256), dot with fc_w
__global__ void k_trip(const int* __restrict__ trip, const float* __restrict__ lw,
                       const float* __restrict__ lb, const float* __restrict__ fw,
                       const float* __restrict__ fb, float* __restrict__ out) {
    int warp = (blockIdx.x * blockDim.x + threadIdx.x) >> 5;
    int l = threadIdx.x & 31;
    if (warp >= NT) return;
    int nodes[4];
#pragma unroll
    for (int q = 0; q < 4; q++) nodes[q] = trip[warp * 4 + q];
    float v[8];
    float sum = 0.f, ssq = 0.f;
#pragma unroll
    for (int j8 = 0; j8 < 8; j8++) {
        int j = j8 * 32 + l;
        v[j8] = g_x2[nodes[j8 >> 1] * HID + (j & 63)];
        sum += v[j8];
        ssq += v[j8] * v[j8];
    }
#pragma unroll
    for (int o = 16; o > 0; o >>= 1) {
        sum += __shfl_xor_sync(~0u, sum, o);
        ssq += __shfl_xor_sync(~0u, ssq, o);
    }
    float mu = sum * (1.f / 256.f);
    float var = ssq * (1.f / 256.f) - mu * mu;
    float inv = rsqrtf(var + EPSN);
    float res = 0.f;
#pragma unroll
    for (int j8 = 0; j8 < 8; j8++) {
        int j = j8 * 32 + l;
        res += ((v[j8] - mu) * inv * lw[j] + lb[j]) * fw[j];
    }
#pragma unroll
    for (int o = 16; o > 0; o >>= 1) res += __shfl_xor_sync(~0u, res, o);
    if (l == 0) out[warp] = res + fb[0];
}

// ---------------- host ----------------------------------------------------
extern "C" void kernel_launch(void* const* d_in, const int* in_sizes, int n_in,
                              void* d_out, int out_size) {
    const float* x   = (const float*)d_in[0];
    // d_in[1] = edge_weight : unused by the reference computation
    const float* W1  = (const float*)d_in[2];
    const float* as1 = (const float*)d_in[3];
    const float* ad1 = (const float*)d_in[4];
    const float* b1  = (const float*)d_in[5];
    const float* W2  = (const float*)d_in[6];
    const float* as2 = (const float*)d_in[7];
    const float* ad2 = (const float*)d_in[8];
    const float* b2  = (const float*)d_in[9];
    const float* g1w = (const float*)d_in[10];
    const float* g1b = (const float*)d_in[11];
    const float* g1s = (const float*)d_in[12];
    const float* g2w = (const float*)d_in[13];
    const float* g2b = (const float*)d_in[14];
    const float* g2s = (const float*)d_in[15];
    const float* lnw = (const float*)d_in[16];
    const float* lnb = (const float*)d_in[17];
    const float* fcw = (const float*)d_in[18];
    const float* fcb = (const float*)d_in[19];
    const int*   ei  = (const int*)d_in[20];
    const int*   trp = (const int*)d_in[21];
    float* out = (float*)d_out;

    // ---- init (zero + wt projections) + CSR build ----
    k_init<<<320, 256>>>(W1, as1, ad1, W2, as2, ad2);
    k_hist<<<(NET + 255) / 256, 256>>>(ei);
    k_scan1<<<SCAN_BLKS, SCAN_CHUNK>>>();
    k_scan2<<<1, 32>>>();
    k_scan3<<<SCAN_BLKS, SCAN_CHUNK>>>();
    k_scatter<<<(NET + 255) / 256, 256>>>(ei);

    // ---- layer 1 ----
    k_gemm1<<<(NN + 31) / 32, 256>>>(x, W1);
    k_gat<<<(NN + 15) / 16, 512>>>(b1, 0);
    k_norm<<<(NN * HID + 255) / 256, 256>>>(g1w, g1b, g1s, 0);

    // ---- layer 2 ----
    k_gemm2<<<(NN + 31) / 32, 256>>>(W2);
    k_gat<<<(NN + 15) / 16, 512>>>(b2, 128);
    k_norm<<<(NN * HID + 255) / 256, 256>>>(g2w, g2b, g2s, 128);

    // ---- triplet head ----
    k_trip<<<(NT * 32 + 255) / 256, 256>>>(trp, lnw, lnb, fcw, fcb, out);
}